// round 13
// baseline (speedup 1.0000x reference)
#include <cuda_runtime.h>

#define HW       64
#define NPIX     4096
#define NTASK    24
#define BT       512
#define IPT      8
#define EDGE_CAP 12288
#define KMAX     (EDGE_CAP / BT)
#define FULL     0xFFFFFFFFu

struct TaskRes { double s2; float pmax; float vfirst; int has; };
__device__ TaskRes g_res[NTASK];
__device__ unsigned g_ctr = 0;   // self-resetting completion counter

struct Shm {
    unsigned           key[NPIX];     // 30-bit sort key by pixel
    unsigned           bcnt[NPIX];    // bucket counts -> claimY (Kruskal, no init)
    unsigned           bstart[NPIX];  // bucket starts -> claimE (Kruskal, no init)
    unsigned short     order[NPIX];   // pixels by rank
    unsigned short     rank[NPIX];    // rank by pixel
    unsigned short     F[NPIX];       // basin root (local min) by pixel
    float              val[NPIX];     // filtration value (negated for variant 1)
    unsigned short     mpar[NPIX];    // minima union-find parent
    unsigned long long edges[EDGE_CAP]; // (valbits<<24)|(a<<12)|b (unordered)
    unsigned short     ekey[EDGE_CAP]; // INVERTED edge rank key = 0xFFFF-(t*8+j)
    double             rS2[16];
    float              rPM[16];
    int                rHas[16];
    int                wsum[32];
    int                ne;
};

__device__ __forceinline__ int phfind(unsigned short* par, int a) {
    int p = par[a];
    while (p != a) {                       // path halving (benign races)
        int g = par[p];
        par[a] = (unsigned short)g;
        a = g; p = par[a];
    }
    return a;
}

__global__ __launch_bounds__(BT) void uf_kernel(const float* __restrict__ x,
                                                float* __restrict__ out)
{
    extern __shared__ char raw[];
    Shm& sh = *(Shm*)raw;

    const int task    = blockIdx.x;
    const int img     = task >> 1;
    const int variant = task & 1;          // 0: sublevel v (8-conn); 1: sublevel -v (4-conn)
    const int b       = img / 3;
    const int c       = img % 3 + 1;
    const float* v    = x + (size_t)(b * 4 + c) * NPIX;
    const int tid     = threadIdx.x;
    const int lane    = tid & 31, warp = tid >> 5;
    const int nOff    = variant ? 4 : 8;

    const int drs[8] = {-1, 1, 0, 0, -1, -1, 1, 1};
    const int dcs[8] = { 0, 0,-1, 1, -1,  1,-1, 1};

    // ---- phase A: zero histogram; vector load; key/val/mpar; bucket --------
#pragma unroll
    for (int i = 0; i < IPT; i++) sh.bcnt[tid * IPT + i] = 0;
    if (tid < 32) sh.wsum[tid] = 0;
    if (tid == 0) sh.ne = 0;
    __syncthreads();

    float4 va0 = ((const float4*)v)[tid * 2];
    float4 va1 = ((const float4*)v)[tid * 2 + 1];
    float vraw[IPT] = {va0.x, va0.y, va0.z, va0.w, va1.x, va1.y, va1.z, va1.w};
    unsigned bloc[IPT];
#pragma unroll
    for (int i = 0; i < IPT; i++) {
        int p = tid * IPT + i;
        float val = vraw[i];
        unsigned bits = __float_as_uint(val);                // monotone for v >= 0
        sh.key[p] = (variant ? ~bits : bits) & 0x3FFFFFFFu;
        unsigned bk = (unsigned)fminf(val * 4096.0f, 4095.0f); // uniform in value
        if (variant) bk = 4095u - bk;                        // descending order
        bloc[i] = bk;
        sh.val[p]  = variant ? -val : val;
        sh.mpar[p] = (unsigned short)p;
        atomicAdd(&sh.bcnt[bk], 1u);
    }
    __syncthreads();

    // ---- phase B: exclusive scan of 4096 bucket counts (16 warps) ----------
    {
        unsigned s = 0;
#pragma unroll
        for (int i = 0; i < IPT; i++) s += sh.bcnt[tid * IPT + i];
        unsigned incl = s;
#pragma unroll
        for (int d = 1; d < 32; d <<= 1) {
            unsigned n = __shfl_up_sync(FULL, incl, d);
            if (lane >= d) incl += n;
        }
        if (lane == 31) sh.wsum[warp] = (int)incl;
        __syncthreads();
        if (tid < 32) {                      // entries 16..31 are zero
            int t = sh.wsum[tid];
            int e = t;
#pragma unroll
            for (int d = 1; d < 32; d <<= 1) {
                int n = __shfl_up_sync(FULL, e, d);
                if (lane >= d) e += n;
            }
            sh.wsum[tid] = e - t;            // exclusive
        }
        __syncthreads();
        unsigned run = (unsigned)sh.wsum[warp] + incl - s;
#pragma unroll
        for (int i = 0; i < IPT; i++) {
            int bk = tid * IPT + i;
            unsigned cb = sh.bcnt[bk];
            sh.bstart[bk] = run;
            run += cb;
            sh.bcnt[bk] = 0;                 // reset for scatter
        }
    }
    __syncthreads();

    // ---- phase C: scatter pixels into order[] (unstable within bucket) -----
#pragma unroll
    for (int i = 0; i < IPT; i++) {
        int p = tid * IPT + i;
        unsigned bk = bloc[i];
        unsigned pos = sh.bstart[bk] + atomicAdd(&sh.bcnt[bk], 1u);
        sh.order[pos] = (unsigned short)p;
    }
    __syncthreads();

    // ---- phase D: per-bucket fixup + rank assignment ------------------------
#pragma unroll
    for (int i = 0; i < IPT; i++) {
        int bk = tid * IPT + i;
        unsigned cb = sh.bcnt[bk];
        unsigned s0 = sh.bstart[bk];
        if (cb == 1) {
            sh.rank[sh.order[s0]] = (unsigned short)s0;
        } else if (cb > 1) {                 // Poisson(1): tiny buckets
            for (unsigned a = 1; a < cb; a++) {
                unsigned short px = sh.order[s0 + a];
                unsigned long long kx =
                    ((unsigned long long)sh.key[px] << 12) | px;
                int j = (int)a - 1;
                while (j >= 0) {
                    unsigned short py = sh.order[s0 + j];
                    unsigned long long ky =
                        ((unsigned long long)sh.key[py] << 12) | py;
                    if (ky <= kx) break;
                    sh.order[s0 + j + 1] = py;
                    j--;
                }
                sh.order[s0 + j + 1] = px;
            }
            for (unsigned a = 0; a < cb; a++)
                sh.rank[sh.order[s0 + a]] = (unsigned short)(s0 + a);
        }
    }
    __syncthreads();

    // ---- steepest-descent pointer: min-rank strictly-lower neighbor --------
#pragma unroll
    for (int i = 0; i < IPT; i++) {
        int p = tid * IPT + i;
        int r = p >> 6, cc = p & 63;
        int best = p, bestr = sh.rank[p];
        for (int k = 0; k < nOff; k++) {
            int rr = r + drs[k], c2 = cc + dcs[k];
            if (rr >= 0 && rr < HW && c2 >= 0 && c2 < HW) {
                int q  = rr * HW + c2;
                int rq = sh.rank[q];
                if (rq < bestr) { bestr = rq; best = q; }
            }
        }
        sh.F[p] = (unsigned short)best;
    }
    __syncthreads();

    // ---- pointer jumping until converged (benign forward-jump races) -------
    int changed = 1;
    while (__syncthreads_or(changed)) {
        changed = 0;
#pragma unroll
        for (int i = 0; i < IPT; i++) {
            int p = tid * IPT + i;
            int f = sh.F[p];
            int g = sh.F[f];
            if (g != f) { sh.F[p] = (unsigned short)g; changed = 1; }
        }
    }

    // ---- single-pass edge emission (per-thread atomic slot alloc) ----------
#pragma unroll
    for (int i = 0; i < IPT; i++) {
        int p = tid * IPT + i;
        int t = sh.rank[p];
        int r = p >> 6, cc = p & 63;
        unsigned short fs[8]; int nf = 0;
        for (int k = 0; k < nOff; k++) {
            int rr = r + drs[k], c2 = cc + dcs[k];
            if (rr >= 0 && rr < HW && c2 >= 0 && c2 < HW) {
                int q = rr * HW + c2;
                if (sh.rank[q] < t) {
                    unsigned short f = sh.F[q];
                    bool dup = false;
                    for (int j = 0; j < nf; j++) if (fs[j] == f) dup = true;
                    if (!dup) fs[nf++] = f;
                }
            }
        }
        if (nf >= 2) {
            int base = atomicAdd(&sh.ne, nf - 1);
            unsigned long long vb =
                ((unsigned long long)__float_as_uint(sh.val[p]) << 24) |
                ((unsigned long long)fs[0] << 12);
            for (int j = 1; j < nf; j++) {
                int slot = base + j - 1;
                if (slot < EDGE_CAP) {
                    sh.edges[slot] = vb | fs[j];
                    // inverted key: earliest edge = LARGEST value (atomicMax)
                    sh.ekey[slot]  = (unsigned short)(0xFFFFu - (t * 8 + j));
                }
            }
        }
    }
    __syncthreads();

    // ---- block-wide parallel Kruskal (ascending-prefix atomicMax claims) ---
    // claimY/claimE alias bcnt/bstart; stale contents (<0x10000) never beat a
    // current-round claim, so NO initialization sweep is needed.
    {
        unsigned short*       mpar   = sh.mpar;
        const unsigned short* rank   = sh.rank;
        unsigned*             claimY = sh.bcnt;
        unsigned*             claimE = sh.bstart;
        const int ne = sh.ne < EDGE_CAP ? sh.ne : EDGE_CAP;

        double S2 = 0.0; float pmax = 0.f; int has = 0;

        unsigned actmask = 0;
#pragma unroll
        for (int k = 0; k < KMAX; k++)
            if (tid + k * BT < ne) actmask |= 1u << k;

        unsigned prefix = 0x10000u;          // grows each round
        int any = (actmask != 0);
        while (__syncthreads_or(any)) {
            // phase 1: find roots, drop dead edges, post claims (atomicMax)
#pragma unroll
            for (int k = 0; k < KMAX; k++) if (actmask & (1u << k)) {
                int slot = tid + k * BT;
                unsigned long long rec = sh.edges[slot];
                int fa = phfind(mpar, (int)((rec >> 12) & 0xFFFu));
                int fb = phfind(mpar, (int)(rec & 0xFFFu));
                if (fa == fb) { actmask &= ~(1u << k); continue; }
                int eld, yng;
                if (rank[fa] < rank[fb]) { eld = fa; yng = fb; }
                else                     { eld = fb; yng = fa; }
                unsigned kk = prefix | sh.ekey[slot];
                atomicMax(&claimY[yng], kk);  // I want to merge yng away
                atomicMax(&claimE[eld], kk);  // I currently see eld as elder
            }
            __syncthreads();
            // phase 2: re-find (roots unchanged within round; claimY==kk can
            // only match this edge's own phase-1 young, so concurrent commits
            // cannot cause spurious or missed commits)
#pragma unroll
            for (int k = 0; k < KMAX; k++) if (actmask & (1u << k)) {
                int slot = tid + k * BT;
                unsigned long long rec = sh.edges[slot];
                int fa = phfind(mpar, (int)((rec >> 12) & 0xFFFu));
                int fb = phfind(mpar, (int)(rec & 0xFFFu));
                if (fa == fb) { actmask &= ~(1u << k); continue; }
                int eld, yng;
                if (rank[fa] < rank[fb]) { eld = fa; yng = fb; }
                else                     { eld = fb; yng = fa; }
                unsigned kk = prefix | sh.ekey[slot];
                // commit iff I won yng's young-claim AND no earlier current-
                // round edge holds yng as its elder
                if (claimY[yng] == kk && claimE[yng] <= kk) {
                    float vv = __uint_as_float((unsigned)(rec >> 24));
                    float p  = vv - sh.val[yng];  // birth = young root's value
                    if (p > 0.f) {
                        S2 += (double)p * (double)p;
                        if (p > pmax) pmax = p;
                        has = 1;
                    }
                    mpar[yng] = (unsigned short)eld;
                    actmask &= ~(1u << k);
                }
            }
            __syncthreads();                  // commits visible before next round
            prefix += 0x10000u;               // stale claims auto-expire
            any = (actmask != 0);
        }

        // block reduction (16 warps)
#pragma unroll
        for (int off = 16; off; off >>= 1) {
            S2 += __shfl_down_sync(FULL, S2, off);
            float pm = __shfl_down_sync(FULL, pmax, off);
            pmax = fmaxf(pmax, pm);
            has |= __shfl_down_sync(FULL, has, off);
        }
        if (lane == 0) { sh.rS2[warp] = S2; sh.rPM[warp] = pmax; sh.rHas[warp] = has; }
        __syncthreads();

        if (tid == 0) {
            double tS2 = 0.0; float tPM = 0.f; int tH = 0;
            for (int w = 0; w < 16; w++) {
                tS2 += sh.rS2[w];
                tPM  = fmaxf(tPM, sh.rPM[w]);
                tH  |= sh.rHas[w];
            }
            TaskRes r;
            r.s2 = tS2; r.pmax = tPM; r.has = tH;
            r.vfirst = sh.val[sh.order[0]];       // essential birth (global min)
            g_res[task] = r;
            __threadfence();
            unsigned old = atomicAdd(&g_ctr, 1u);
            if (old == NTASK - 1) {               // last block: compute the loss
                __threadfence();
                volatile TaskRes* gr = g_res;
                const int nfx[3] = {0, 0, 1};
                const int nf1[3] = {0, 1, 0};
                double loss = 0.0;
                for (int im = 0; im < 12; im++) {
                    int ci = im % 3;
                    double s2a = gr[im*2].s2;   float pma = gr[im*2].pmax;
                    int    ha  = gr[im*2].has;  float vf  = gr[im*2].vfirst;
                    double s2b = gr[im*2+1].s2; float pmb = gr[im*2+1].pmax;
                    int    hb  = gr[im*2+1].has;
                    double h0 = (double)vf * (double)vf + s2a;
                    if (nfx[ci]) {
                        if (ha) { double p = pma; h0 += (1.0-p)*(1.0-p) - p*p; }
                        else     h0 += 1.0;
                    }
                    double h1 = s2b;
                    if (nf1[ci]) {
                        if (hb) { double p = pmb; h1 += (1.0-p)*(1.0-p) - p*p; }
                        else     h1 += 1.0;
                    }
                    loss += h0 + h1;
                }
                out[0] = (float)(loss * 0.25);
                atomicSub(&g_ctr, (unsigned)NTASK);   // reset for next launch
            }
        }
    }
}

extern "C" void kernel_launch(void* const* d_in, const int* in_sizes, int n_in,
                              void* d_out, int out_size)
{
    (void)in_sizes; (void)n_in; (void)out_size;
    const float* x = (const float*)d_in[0];
    cudaFuncSetAttribute(uf_kernel, cudaFuncAttributeMaxDynamicSharedMemorySize,
                         (int)sizeof(Shm));
    uf_kernel<<<NTASK, BT, sizeof(Shm)>>>(x, (float*)d_out);
}

// round 14
// speedup vs baseline: 1.6310x; 1.6310x over previous
#include <cuda_runtime.h>

#define HW       64
#define NPIX     4096
#define NTASK    24
#define BT       1024
#define IPT      4
#define EDGE_CAP 12288
#define KMAX     (EDGE_CAP / BT)
#define FULL     0xFFFFFFFFu

struct TaskRes { double s2; float pmax; float vfirst; int has; };
__device__ TaskRes g_res[NTASK];
__device__ unsigned g_ctr = 0;   // self-resetting completion counter

struct Shm {
    unsigned           key[NPIX];     // 30-bit sort key by pixel
    unsigned           bcnt[NPIX];    // bucket counts -> claimY (Kruskal)
    unsigned           bstart[NPIX];  // bucket starts -> claimE (Kruskal)
    unsigned short     order[NPIX];   // pixels by rank
    unsigned short     rank[NPIX];    // rank by pixel
    unsigned short     F[NPIX];       // basin root (local min) by pixel
    float              val[NPIX];     // filtration value (negated for variant 1)
    unsigned short     mpar[NPIX];    // minima union-find parent
    unsigned long long edges[EDGE_CAP]; // (valbits<<24)|(a<<12)|b (unordered)
    unsigned short     ekey[EDGE_CAP]; // edge rank key = t*8 + j (total order)
    double             rS2[32];
    float              rPM[32];
    int                rHas[32];
    int                wsum[32];
    int                ne;
};

__device__ __forceinline__ int phfind(unsigned short* par, int a) {
    int p = par[a];
    while (p != a) {                       // path halving (benign races)
        int g = par[p];
        par[a] = (unsigned short)g;
        a = g; p = par[a];
    }
    return a;
}

__global__ __launch_bounds__(BT) void uf_kernel(const float* __restrict__ x,
                                                float* __restrict__ out)
{
    extern __shared__ char raw[];
    Shm& sh = *(Shm*)raw;

    const int task    = blockIdx.x;
    const int img     = task >> 1;
    const int variant = task & 1;          // 0: sublevel v (8-conn); 1: sublevel -v (4-conn)
    const int b       = img / 3;
    const int c       = img % 3 + 1;
    const float* v    = x + (size_t)(b * 4 + c) * NPIX;
    const int tid     = threadIdx.x;
    const int lane    = tid & 31, warp = tid >> 5;
    const int nOff    = variant ? 4 : 8;

    const int drs[8] = {-1, 1, 0, 0, -1, -1, 1, 1};
    const int dcs[8] = { 0, 0,-1, 1, -1,  1,-1, 1};

    // ---- phase A: zero histogram; vector load; key; VALUE-uniform bucket ---
#pragma unroll
    for (int i = 0; i < IPT; i++) sh.bcnt[tid * IPT + i] = 0;
    if (tid == 0) sh.ne = 0;
    __syncthreads();

    float4 vin = ((const float4*)v)[tid];      // p = tid*4 .. tid*4+3
    float    vloc[IPT] = {vin.x, vin.y, vin.z, vin.w};
    unsigned bloc[IPT];
#pragma unroll
    for (int i = 0; i < IPT; i++) {
        int p = tid * IPT + i;
        float val = vloc[i];
        unsigned bits = __float_as_uint(val);                // monotone for v >= 0
        sh.key[p] = (variant ? ~bits : bits) & 0x3FFFFFFFu;
        unsigned bk = (unsigned)fminf(val * 4096.0f, 4095.0f); // uniform in value
        if (variant) bk = 4095u - bk;                        // descending order
        bloc[i] = bk;
        if (variant) vloc[i] = -val;
        atomicAdd(&sh.bcnt[bk], 1u);
    }
    __syncthreads();

    // ---- phase B: exclusive scan of 4096 bucket counts ---------------------
    {
        unsigned s = 0;
#pragma unroll
        for (int i = 0; i < IPT; i++) s += sh.bcnt[tid * IPT + i];
        unsigned incl = s;
#pragma unroll
        for (int d = 1; d < 32; d <<= 1) {
            unsigned n = __shfl_up_sync(FULL, incl, d);
            if (lane >= d) incl += n;
        }
        if (lane == 31) sh.wsum[warp] = (int)incl;
        __syncthreads();
        if (tid < 32) {
            int t = sh.wsum[tid];
            int e = t;
#pragma unroll
            for (int d = 1; d < 32; d <<= 1) {
                int n = __shfl_up_sync(FULL, e, d);
                if (lane >= d) e += n;
            }
            sh.wsum[tid] = e - t;                  // exclusive
        }
        __syncthreads();
        unsigned run = (unsigned)sh.wsum[warp] + incl - s;
#pragma unroll
        for (int i = 0; i < IPT; i++) {
            int bk = tid * IPT + i;
            unsigned cb = sh.bcnt[bk];
            sh.bstart[bk] = run;
            run += cb;
            sh.bcnt[bk] = 0;                       // reset for scatter
        }
    }
    __syncthreads();

    // ---- phase C: scatter pixels into order[] (unstable within bucket) -----
#pragma unroll
    for (int i = 0; i < IPT; i++) {
        int p = tid * IPT + i;
        unsigned bk = bloc[i];
        unsigned pos = sh.bstart[bk] + atomicAdd(&sh.bcnt[bk], 1u);
        sh.order[pos] = (unsigned short)p;
    }
    __syncthreads();

    // ---- phase D: per-bucket fixup (stable order by (key30, idx)) ----------
#pragma unroll
    for (int i = 0; i < IPT; i++) {
        int bk = tid * IPT + i;
        unsigned cb = sh.bcnt[bk];
        if (cb > 1) {                              // Poisson(1): tiny buckets
            unsigned s0 = sh.bstart[bk];
            for (unsigned a = 1; a < cb; a++) {
                unsigned short px = sh.order[s0 + a];
                unsigned long long kx =
                    ((unsigned long long)sh.key[px] << 12) | px;
                int j = (int)a - 1;
                while (j >= 0) {
                    unsigned short py = sh.order[s0 + j];
                    unsigned long long ky =
                        ((unsigned long long)sh.key[py] << 12) | py;
                    if (ky <= kx) break;
                    sh.order[s0 + j + 1] = py;
                    j--;
                }
                sh.order[s0 + j + 1] = px;
            }
        }
    }
    __syncthreads();

    // ---- phase E: rank / val / mpar; claimY/claimE alias bcnt/bstart -------
#pragma unroll
    for (int i = 0; i < IPT; i++) {
        int t = tid * IPT + i;
        sh.rank[sh.order[t]] = (unsigned short)t;
        int p = t;
        sh.val[p]    = vloc[i];
        sh.mpar[p]   = (unsigned short)p;
        sh.bcnt[p]   = FULL;                       // claimY
        sh.bstart[p] = FULL;                       // claimE
    }
    __syncthreads();

    // ---- steepest-descent pointer: min-rank strictly-lower neighbor --------
#pragma unroll
    for (int i = 0; i < IPT; i++) {
        int p = tid * IPT + i;
        int r = p >> 6, cc = p & 63;
        int best = p, bestr = sh.rank[p];
        for (int k = 0; k < nOff; k++) {
            int rr = r + drs[k], c2 = cc + dcs[k];
            if (rr >= 0 && rr < HW && c2 >= 0 && c2 < HW) {
                int q  = rr * HW + c2;
                int rq = sh.rank[q];
                if (rq < bestr) { bestr = rq; best = q; }
            }
        }
        sh.F[p] = (unsigned short)best;
    }
    __syncthreads();

    // ---- pointer jumping, two doubling steps per barrier round -------------
    int changed = 1;
    while (__syncthreads_or(changed)) {
        changed = 0;
#pragma unroll
        for (int i = 0; i < IPT; i++) {
            int p = tid * IPT + i;
            int f = sh.F[p];
            int g = sh.F[f];
            int h = sh.F[g];                       // second jump (benign races)
            if (h != f) { sh.F[p] = (unsigned short)h; changed = 1; }
        }
    }

    // ---- single-pass edge emission (per-thread atomic slot alloc) ----------
#pragma unroll
    for (int i = 0; i < IPT; i++) {
        int p = tid * IPT + i;
        int t = sh.rank[p];
        int r = p >> 6, cc = p & 63;
        unsigned short fs[8]; int nf = 0;
        for (int k = 0; k < nOff; k++) {
            int rr = r + drs[k], c2 = cc + dcs[k];
            if (rr >= 0 && rr < HW && c2 >= 0 && c2 < HW) {
                int q = rr * HW + c2;
                if (sh.rank[q] < t) {
                    unsigned short f = sh.F[q];
                    bool dup = false;
                    for (int j = 0; j < nf; j++) if (fs[j] == f) dup = true;
                    if (!dup) fs[nf++] = f;
                }
            }
        }
        if (nf >= 2) {
            int base = atomicAdd(&sh.ne, nf - 1);
            unsigned long long vb =
                ((unsigned long long)__float_as_uint(sh.val[p]) << 24) |
                ((unsigned long long)fs[0] << 12);
            for (int j = 1; j < nf; j++) {
                int slot = base + j - 1;
                if (slot < EDGE_CAP) {
                    sh.edges[slot] = vb | fs[j];
                    sh.ekey[slot]  = (unsigned short)(t * 8 + j); // total order
                }
            }
        }
    }
    __syncthreads();

    // ---- block-wide parallel Kruskal (round-prefixed role-split claims) ----
    {
        unsigned short*       mpar   = sh.mpar;
        const unsigned short* rank   = sh.rank;
        unsigned*             claimY = sh.bcnt;
        unsigned*             claimE = sh.bstart;
        const int ne = sh.ne < EDGE_CAP ? sh.ne : EDGE_CAP;

        double S2 = 0.0; float pmax = 0.f; int has = 0;

        unsigned actmask = 0;
        unsigned short ya[KMAX], ea[KMAX];
        unsigned       kk[KMAX];
        float          va[KMAX];
#pragma unroll
        for (int k = 0; k < KMAX; k++)
            if (tid + k * BT < ne) actmask |= 1u << k;

        unsigned prefix = 0xFFFF0000u;   // decreases each round -> stale claims
                                         // always look "larger than any current"
        int any = (actmask != 0);
        while (__syncthreads_or(any)) {
            unsigned claimed = 0;
            // phase 1: find roots, drop dead edges, post prefixed claims
#pragma unroll
            for (int k = 0; k < KMAX; k++) if (actmask & (1u << k)) {
                int slot = tid + k * BT;
                unsigned long long rec = sh.edges[slot];
                int fa = phfind(mpar, (int)((rec >> 12) & 0xFFFu));
                int fb = phfind(mpar, (int)(rec & 0xFFFu));
                if (fa == fb) { actmask &= ~(1u << k); continue; }
                int eld, yng;
                if (rank[fa] < rank[fb]) { eld = fa; yng = fb; }
                else                     { eld = fb; yng = fa; }
                ya[k] = (unsigned short)yng;
                ea[k] = (unsigned short)eld;
                va[k] = __uint_as_float((unsigned)(rec >> 24));
                kk[k] = prefix | sh.ekey[slot];
                atomicMin(&claimY[yng], kk[k]);   // I want to merge yng away
                atomicMin(&claimE[eld], kk[k]);   // I currently see eld as elder
                claimed |= 1u << k;
            }
            __syncthreads();
            // phase 2: commit iff (1) min young-claim of y is me (this round)
            //                     (2) no current-round edge has y as elder
            //          elder sharing is free -> whole stars commit per round
#pragma unroll
            for (int k = 0; k < KMAX; k++) if (claimed & (1u << k)) {
                if (claimY[ya[k]] == kk[k] && claimE[ya[k]] > kk[k]) {
                    int yng = ya[k];
                    float p = va[k] - sh.val[yng]; // birth = young root's value
                    if (p > 0.f) {
                        S2 += (double)p * (double)p;
                        if (p > pmax) pmax = p;
                        has = 1;
                    }
                    mpar[yng] = ea[k];
                    actmask &= ~(1u << k);
                }
            }
            __syncthreads();                 // commits visible before next refind
            prefix -= 0x10000u;              // no claim reset needed
            any = (actmask != 0);
        }

        // block reduction
#pragma unroll
        for (int off = 16; off; off >>= 1) {
            S2 += __shfl_down_sync(FULL, S2, off);
            float pm = __shfl_down_sync(FULL, pmax, off);
            pmax = fmaxf(pmax, pm);
            has |= __shfl_down_sync(FULL, has, off);
        }
        if (lane == 0) { sh.rS2[warp] = S2; sh.rPM[warp] = pmax; sh.rHas[warp] = has; }
        __syncthreads();

        if (tid == 0) {
            double tS2 = 0.0; float tPM = 0.f; int tH = 0;
            for (int w = 0; w < 32; w++) {
                tS2 += sh.rS2[w];
                tPM  = fmaxf(tPM, sh.rPM[w]);
                tH  |= sh.rHas[w];
            }
            TaskRes r;
            r.s2 = tS2; r.pmax = tPM; r.has = tH;
            r.vfirst = sh.val[sh.order[0]];       // essential birth (global min)
            g_res[task] = r;
            __threadfence();
            unsigned old = atomicAdd(&g_ctr, 1u);
            if (old == NTASK - 1) {               // last block: compute the loss
                __threadfence();
                volatile TaskRes* gr = g_res;
                const int nfx[3] = {0, 0, 1};
                const int nf1[3] = {0, 1, 0};
                double loss = 0.0;
                for (int im = 0; im < 12; im++) {
                    int ci = im % 3;
                    double s2a = gr[im*2].s2;   float pma = gr[im*2].pmax;
                    int    ha  = gr[im*2].has;  float vf  = gr[im*2].vfirst;
                    double s2b = gr[im*2+1].s2; float pmb = gr[im*2+1].pmax;
                    int    hb  = gr[im*2+1].has;
                    double h0 = (double)vf * (double)vf + s2a;
                    if (nfx[ci]) {
                        if (ha) { double p = pma; h0 += (1.0-p)*(1.0-p) - p*p; }
                        else     h0 += 1.0;
                    }
                    double h1 = s2b;
                    if (nf1[ci]) {
                        if (hb) { double p = pmb; h1 += (1.0-p)*(1.0-p) - p*p; }
                        else     h1 += 1.0;
                    }
                    loss += h0 + h1;
                }
                out[0] = (float)(loss * 0.25);
                atomicSub(&g_ctr, (unsigned)NTASK);   // reset for next launch
            }
        }
    }
}

extern "C" void kernel_launch(void* const* d_in, const int* in_sizes, int n_in,
                              void* d_out, int out_size)
{
    (void)in_sizes; (void)n_in; (void)out_size;
    const float* x = (const float*)d_in[0];
    cudaFuncSetAttribute(uf_kernel, cudaFuncAttributeMaxDynamicSharedMemorySize,
                         (int)sizeof(Shm));
    uf_kernel<<<NTASK, BT, sizeof(Shm)>>>(x, (float*)d_out);
}

// round 15
// speedup vs baseline: 1.6683x; 1.0229x over previous
#include <cuda_runtime.h>

#define HW       64
#define NPIX     4096
#define NTASK    24
#define BT       1024
#define IPT      4
#define EDGE_CAP 12288
#define KMAX     (EDGE_CAP / BT)
#define FULL     0xFFFFFFFFu

struct TaskRes { double s2; float pmax; float vfirst; int has; };
__device__ TaskRes g_res[NTASK];
__device__ unsigned g_ctr = 0;   // self-resetting completion counter

struct Shm {
    unsigned           key[NPIX];     // 30-bit sort key by pixel
    unsigned           bcnt[NPIX];    // bucket counts -> claimY (Kruskal)
    unsigned           bstart[NPIX];  // bucket starts -> claimE (Kruskal)
    unsigned short     order[NPIX];   // pixels by rank
    unsigned short     rank[NPIX];    // rank by pixel
    unsigned short     F[NPIX];       // basin root (local min) by pixel
    float              val[NPIX];     // filtration value (negated for variant 1)
    unsigned short     mpar[NPIX];    // minima union-find parent
    unsigned long long edges[EDGE_CAP]; // (valbits<<24)|(a<<12)|b (unordered)
    unsigned short     ekey[EDGE_CAP]; // edge rank key = t*8 + j (total order)
    double             rS2[32];
    float              rPM[32];
    int                rHas[32];
    int                wsum[32];
    int                ne;
};

__device__ __forceinline__ int phfind(unsigned short* par, int a) {
    int p = par[a];
    while (p != a) {                       // path halving (benign races)
        int g = par[p];
        par[a] = (unsigned short)g;
        a = g; p = par[a];
    }
    return a;
}

__global__ __launch_bounds__(BT) void uf_kernel(const float* __restrict__ x,
                                                float* __restrict__ out)
{
    extern __shared__ char raw[];
    Shm& sh = *(Shm*)raw;

    const int task    = blockIdx.x;
    const int img     = task >> 1;
    const int variant = task & 1;          // 0: sublevel v (8-conn); 1: sublevel -v (4-conn)
    const int b       = img / 3;
    const int c       = img % 3 + 1;
    const float* v    = x + (size_t)(b * 4 + c) * NPIX;
    const int tid     = threadIdx.x;
    const int lane    = tid & 31, warp = tid >> 5;
    const int nOff    = variant ? 4 : 8;

    const int drs[8] = {-1, 1, 0, 0, -1, -1, 1, 1};
    const int dcs[8] = { 0, 0,-1, 1, -1,  1,-1, 1};

    // ---- phase A: zero histogram; vector load; key; VALUE-uniform bucket ---
#pragma unroll
    for (int i = 0; i < IPT; i++) sh.bcnt[tid * IPT + i] = 0;
    if (tid == 0) sh.ne = 0;
    __syncthreads();

    float4 vin = ((const float4*)v)[tid];      // p = tid*4 .. tid*4+3
    float    vloc[IPT] = {vin.x, vin.y, vin.z, vin.w};
    unsigned bloc[IPT];
#pragma unroll
    for (int i = 0; i < IPT; i++) {
        int p = tid * IPT + i;
        float val = vloc[i];
        unsigned bits = __float_as_uint(val);                // monotone for v >= 0
        sh.key[p] = (variant ? ~bits : bits) & 0x3FFFFFFFu;
        unsigned bk = (unsigned)fminf(val * 4096.0f, 4095.0f); // uniform in value
        if (variant) bk = 4095u - bk;                        // descending order
        bloc[i] = bk;
        if (variant) vloc[i] = -val;
        atomicAdd(&sh.bcnt[bk], 1u);
    }
    __syncthreads();

    // ---- phase B: exclusive scan of 4096 bucket counts ---------------------
    {
        unsigned s = 0;
#pragma unroll
        for (int i = 0; i < IPT; i++) s += sh.bcnt[tid * IPT + i];
        unsigned incl = s;
#pragma unroll
        for (int d = 1; d < 32; d <<= 1) {
            unsigned n = __shfl_up_sync(FULL, incl, d);
            if (lane >= d) incl += n;
        }
        if (lane == 31) sh.wsum[warp] = (int)incl;
        __syncthreads();
        if (tid < 32) {
            int t = sh.wsum[tid];
            int e = t;
#pragma unroll
            for (int d = 1; d < 32; d <<= 1) {
                int n = __shfl_up_sync(FULL, e, d);
                if (lane >= d) e += n;
            }
            sh.wsum[tid] = e - t;                  // exclusive
        }
        __syncthreads();
        unsigned run = (unsigned)sh.wsum[warp] + incl - s;
#pragma unroll
        for (int i = 0; i < IPT; i++) {
            int bk = tid * IPT + i;
            unsigned cb = sh.bcnt[bk];
            sh.bstart[bk] = run;
            run += cb;
            sh.bcnt[bk] = 0;                       // reset for scatter
        }
    }
    __syncthreads();

    // ---- phase C: scatter pixels into order[] (unstable within bucket) -----
#pragma unroll
    for (int i = 0; i < IPT; i++) {
        int p = tid * IPT + i;
        unsigned bk = bloc[i];
        unsigned pos = sh.bstart[bk] + atomicAdd(&sh.bcnt[bk], 1u);
        sh.order[pos] = (unsigned short)p;
    }
    __syncthreads();

    // ---- phase D: per-bucket fixup (stable order by (key30, idx)) ----------
#pragma unroll
    for (int i = 0; i < IPT; i++) {
        int bk = tid * IPT + i;
        unsigned cb = sh.bcnt[bk];
        if (cb > 1) {                              // Poisson(1): tiny buckets
            unsigned s0 = sh.bstart[bk];
            for (unsigned a = 1; a < cb; a++) {
                unsigned short px = sh.order[s0 + a];
                unsigned long long kx =
                    ((unsigned long long)sh.key[px] << 12) | px;
                int j = (int)a - 1;
                while (j >= 0) {
                    unsigned short py = sh.order[s0 + j];
                    unsigned long long ky =
                        ((unsigned long long)sh.key[py] << 12) | py;
                    if (ky <= kx) break;
                    sh.order[s0 + j + 1] = py;
                    j--;
                }
                sh.order[s0 + j + 1] = px;
            }
        }
    }
    __syncthreads();

    // ---- phase E: rank / val / mpar; claimY/claimE alias bcnt/bstart -------
#pragma unroll
    for (int i = 0; i < IPT; i++) {
        int t = tid * IPT + i;
        sh.rank[sh.order[t]] = (unsigned short)t;
        int p = t;
        sh.val[p]    = vloc[i];
        sh.mpar[p]   = (unsigned short)p;
        sh.bcnt[p]   = FULL;                       // claimY
        sh.bstart[p] = FULL;                       // claimE
    }
    __syncthreads();

    // ---- steepest-descent pointer: min-rank strictly-lower neighbor --------
#pragma unroll
    for (int i = 0; i < IPT; i++) {
        int p = tid * IPT + i;
        int r = p >> 6, cc = p & 63;
        int best = p, bestr = sh.rank[p];
        for (int k = 0; k < nOff; k++) {
            int rr = r + drs[k], c2 = cc + dcs[k];
            if (rr >= 0 && rr < HW && c2 >= 0 && c2 < HW) {
                int q  = rr * HW + c2;
                int rq = sh.rank[q];
                if (rq < bestr) { bestr = rq; best = q; }
            }
        }
        sh.F[p] = (unsigned short)best;
    }
    __syncthreads();

    // ---- pointer jumping until converged (benign forward-jump races) -------
    int changed = 1;
    while (__syncthreads_or(changed)) {
        changed = 0;
#pragma unroll
        for (int i = 0; i < IPT; i++) {
            int p = tid * IPT + i;
            int f = sh.F[p];
            int g = sh.F[f];
            if (g != f) { sh.F[p] = (unsigned short)g; changed = 1; }
        }
    }

    // ---- single-pass edge emission (per-thread atomic slot alloc) ----------
#pragma unroll
    for (int i = 0; i < IPT; i++) {
        int p = tid * IPT + i;
        int t = sh.rank[p];
        int r = p >> 6, cc = p & 63;
        unsigned short fs[8]; int nf = 0;
        for (int k = 0; k < nOff; k++) {
            int rr = r + drs[k], c2 = cc + dcs[k];
            if (rr >= 0 && rr < HW && c2 >= 0 && c2 < HW) {
                int q = rr * HW + c2;
                if (sh.rank[q] < t) {
                    unsigned short f = sh.F[q];
                    bool dup = false;
                    for (int j = 0; j < nf; j++) if (fs[j] == f) dup = true;
                    if (!dup) fs[nf++] = f;
                }
            }
        }
        if (nf >= 2) {
            int base = atomicAdd(&sh.ne, nf - 1);
            unsigned long long vb =
                ((unsigned long long)__float_as_uint(sh.val[p]) << 24) |
                ((unsigned long long)fs[0] << 12);
            for (int j = 1; j < nf; j++) {
                int slot = base + j - 1;
                if (slot < EDGE_CAP) {
                    sh.edges[slot] = vb | fs[j];
                    sh.ekey[slot]  = (unsigned short)(t * 8 + j); // total order
                }
            }
        }
    }
    __syncthreads();

    // ---- block-wide parallel Kruskal (root-cached, round-prefixed claims) --
    {
        unsigned short*       mpar   = sh.mpar;
        const unsigned short* rank   = sh.rank;
        unsigned*             claimY = sh.bcnt;
        unsigned*             claimE = sh.bstart;
        const int ne = sh.ne < EDGE_CAP ? sh.ne : EDGE_CAP;

        double S2 = 0.0; float pmax = 0.f; int has = 0;

        unsigned actmask = 0;
        unsigned short ya[KMAX], ea[KMAX], kks[KMAX];
        float          va[KMAX];
        // one-time init: load records; cache endpoints (they are minima and
        // thus on the find path forever: find(cached) == find(endpoint))
#pragma unroll
        for (int k = 0; k < KMAX; k++) {
            int slot = tid + k * BT;
            if (slot < ne) {
                unsigned long long rec = sh.edges[slot];
                ya[k]  = (unsigned short)((rec >> 12) & 0xFFFu);
                ea[k]  = (unsigned short)(rec & 0xFFFu);
                va[k]  = __uint_as_float((unsigned)(rec >> 24));
                kks[k] = sh.ekey[slot];
                actmask |= 1u << k;
            }
        }

        unsigned prefix = 0xFFFF0000u;   // decreases each round -> stale claims
                                         // always look "larger than any current"
        int any = (actmask != 0);
        while (__syncthreads_or(any)) {
            unsigned claimed = 0;
            // phase 1: short finds from cached roots, post prefixed claims
#pragma unroll
            for (int k = 0; k < KMAX; k++) if (actmask & (1u << k)) {
                int fa = phfind(mpar, ya[k]);      // 0-2 hops after round 1
                int fb = phfind(mpar, ea[k]);
                if (fa == fb) { actmask &= ~(1u << k); continue; }
                int eld, yng;
                if (rank[fa] < rank[fb]) { eld = fa; yng = fb; }
                else                     { eld = fb; yng = fa; }
                ya[k] = (unsigned short)yng;       // refresh cache
                ea[k] = (unsigned short)eld;
                unsigned kk = prefix | kks[k];
                atomicMin(&claimY[yng], kk);       // I want to merge yng away
                atomicMin(&claimE[eld], kk);       // I currently see eld as elder
                claimed |= 1u << k;
            }
            __syncthreads();
            // phase 2: commit iff (1) min young-claim of y is me (this round)
            //                     (2) no current-round edge has y as elder
            //          elder sharing is free -> whole stars commit per round
#pragma unroll
            for (int k = 0; k < KMAX; k++) if (claimed & (1u << k)) {
                unsigned kk = prefix | kks[k];
                if (claimY[ya[k]] == kk && claimE[ya[k]] > kk) {
                    int yng = ya[k];
                    float p = va[k] - sh.val[yng]; // birth = young root's value
                    if (p > 0.f) {
                        S2 += (double)p * (double)p;
                        if (p > pmax) pmax = p;
                        has = 1;
                    }
                    mpar[yng] = ea[k];
                    actmask &= ~(1u << k);
                }
            }
            __syncthreads();                 // commits visible before next refind
            prefix -= 0x10000u;              // no claim reset needed
            any = (actmask != 0);
        }

        // block reduction
#pragma unroll
        for (int off = 16; off; off >>= 1) {
            S2 += __shfl_down_sync(FULL, S2, off);
            float pm = __shfl_down_sync(FULL, pmax, off);
            pmax = fmaxf(pmax, pm);
            has |= __shfl_down_sync(FULL, has, off);
        }
        if (lane == 0) { sh.rS2[warp] = S2; sh.rPM[warp] = pmax; sh.rHas[warp] = has; }
        __syncthreads();

        if (tid == 0) {
            double tS2 = 0.0; float tPM = 0.f; int tH = 0;
            for (int w = 0; w < 32; w++) {
                tS2 += sh.rS2[w];
                tPM  = fmaxf(tPM, sh.rPM[w]);
                tH  |= sh.rHas[w];
            }
            TaskRes r;
            r.s2 = tS2; r.pmax = tPM; r.has = tH;
            r.vfirst = sh.val[sh.order[0]];       // essential birth (global min)
            g_res[task] = r;
            __threadfence();
            unsigned old = atomicAdd(&g_ctr, 1u);
            if (old == NTASK - 1) {               // last block: compute the loss
                __threadfence();
                volatile TaskRes* gr = g_res;
                const int nfx[3] = {0, 0, 1};
                const int nf1[3] = {0, 1, 0};
                double loss = 0.0;
                for (int im = 0; im < 12; im++) {
                    int ci = im % 3;
                    double s2a = gr[im*2].s2;   float pma = gr[im*2].pmax;
                    int    ha  = gr[im*2].has;  float vf  = gr[im*2].vfirst;
                    double s2b = gr[im*2+1].s2; float pmb = gr[im*2+1].pmax;
                    int    hb  = gr[im*2+1].has;
                    double h0 = (double)vf * (double)vf + s2a;
                    if (nfx[ci]) {
                        if (ha) { double p = pma; h0 += (1.0-p)*(1.0-p) - p*p; }
                        else     h0 += 1.0;
                    }
                    double h1 = s2b;
                    if (nf1[ci]) {
                        if (hb) { double p = pmb; h1 += (1.0-p)*(1.0-p) - p*p; }
                        else     h1 += 1.0;
                    }
                    loss += h0 + h1;
                }
                out[0] = (float)(loss * 0.25);
                atomicSub(&g_ctr, (unsigned)NTASK);   // reset for next launch
            }
        }
    }
}

extern "C" void kernel_launch(void* const* d_in, const int* in_sizes, int n_in,
                              void* d_out, int out_size)
{
    (void)in_sizes; (void)n_in; (void)out_size;
    const float* x = (const float*)d_in[0];
    cudaFuncSetAttribute(uf_kernel, cudaFuncAttributeMaxDynamicSharedMemorySize,
                         (int)sizeof(Shm));
    uf_kernel<<<NTASK, BT, sizeof(Shm)>>>(x, (float*)d_out);
}

// round 16
// speedup vs baseline: 1.6689x; 1.0004x over previous
#include <cuda_runtime.h>

#define HW       64
#define NPIX     4096
#define NTASK    24
#define BT       1024
#define IPT      4
#define EDGE_CAP 12288
#define KMAX     (EDGE_CAP / BT)
#define FULL     0xFFFFFFFFu

struct TaskRes { double s2; float pmax; float vfirst; int has; };
__device__ TaskRes g_res[NTASK];
__device__ unsigned g_ctr = 0;   // self-resetting completion counter

struct Shm {
    unsigned           key[NPIX];     // 30-bit sort key -> claimY (Kruskal)
    unsigned           bcnt[NPIX];    // bucket counts   -> claimE (Kruskal)
    unsigned           bstart[NPIX];  // bucket start positions
    unsigned short     order[NPIX];   // pixels by rank
    unsigned short     rank[NPIX];    // rank by pixel
    unsigned short     F[NPIX];       // basin root (local min) by pixel
    float              val[NPIX];     // filtration value (negated for variant 1)
    unsigned short     mpar[NPIX];    // minima union-find parent
    unsigned long long edges[EDGE_CAP]; // (valbits<<24)|(a<<12)|b (unordered)
    unsigned short     ekey[EDGE_CAP]; // edge rank key = t*8 + j (total order)
    double             rS2[32];
    float              rPM[32];
    int                rHas[32];
    int                wsum[32];
    int                ne;
};

__device__ __forceinline__ int phfind(unsigned short* par, int a) {
    int p = par[a];
    while (p != a) {                       // path halving (benign races)
        int g = par[p];
        par[a] = (unsigned short)g;
        a = g; p = par[a];
    }
    return a;
}

__global__ __launch_bounds__(BT) void uf_kernel(const float* __restrict__ x,
                                                float* __restrict__ out)
{
    extern __shared__ char raw[];
    Shm& sh = *(Shm*)raw;

    const int task    = blockIdx.x;
    const int img     = task >> 1;
    const int variant = task & 1;          // 0: sublevel v (8-conn); 1: sublevel -v (4-conn)
    const int b       = img / 3;
    const int c       = img % 3 + 1;
    const float* v    = x + (size_t)(b * 4 + c) * NPIX;
    const int tid     = threadIdx.x;
    const int lane    = tid & 31, warp = tid >> 5;
    const int nOff    = variant ? 4 : 8;

    const int drs[8] = {-1, 1, 0, 0, -1, -1, 1, 1};
    const int dcs[8] = { 0, 0,-1, 1, -1,  1,-1, 1};

    // ---- phase A: zero histogram; vector load; key/val/mpar; bucket --------
#pragma unroll
    for (int i = 0; i < IPT; i++) sh.bcnt[tid * IPT + i] = 0;
    if (tid == 0) sh.ne = 0;
    __syncthreads();

    float4 vin = ((const float4*)v)[tid];      // p = tid*4 .. tid*4+3
    float    vloc[IPT] = {vin.x, vin.y, vin.z, vin.w};
    unsigned bloc[IPT];
#pragma unroll
    for (int i = 0; i < IPT; i++) {
        int p = tid * IPT + i;
        float val = vloc[i];
        unsigned bits = __float_as_uint(val);                // monotone for v >= 0
        sh.key[p] = (variant ? ~bits : bits) & 0x3FFFFFFFu;
        unsigned bk = (unsigned)fminf(val * 4096.0f, 4095.0f); // uniform in value
        if (variant) bk = 4095u - bk;                        // descending order
        bloc[i] = bk;
        sh.val[p]  = variant ? -val : val;
        sh.mpar[p] = (unsigned short)p;
        atomicAdd(&sh.bcnt[bk], 1u);
    }
    __syncthreads();

    // ---- phase B: exclusive scan of 4096 bucket counts ---------------------
    {
        unsigned s = 0;
#pragma unroll
        for (int i = 0; i < IPT; i++) s += sh.bcnt[tid * IPT + i];
        unsigned incl = s;
#pragma unroll
        for (int d = 1; d < 32; d <<= 1) {
            unsigned n = __shfl_up_sync(FULL, incl, d);
            if (lane >= d) incl += n;
        }
        if (lane == 31) sh.wsum[warp] = (int)incl;
        __syncthreads();
        if (tid < 32) {
            int t = sh.wsum[tid];
            int e = t;
#pragma unroll
            for (int d = 1; d < 32; d <<= 1) {
                int n = __shfl_up_sync(FULL, e, d);
                if (lane >= d) e += n;
            }
            sh.wsum[tid] = e - t;                  // exclusive
        }
        __syncthreads();
        unsigned run = (unsigned)sh.wsum[warp] + incl - s;
#pragma unroll
        for (int i = 0; i < IPT; i++) {
            int bk = tid * IPT + i;
            unsigned cb = sh.bcnt[bk];
            sh.bstart[bk] = run;
            run += cb;
            sh.bcnt[bk] = 0;                       // reset for scatter
        }
    }
    __syncthreads();

    // ---- phase C: scatter pixels into order[] (unstable within bucket) -----
#pragma unroll
    for (int i = 0; i < IPT; i++) {
        int p = tid * IPT + i;
        unsigned bk = bloc[i];
        unsigned pos = sh.bstart[bk] + atomicAdd(&sh.bcnt[bk], 1u);
        sh.order[pos] = (unsigned short)p;
    }
    __syncthreads();

    // ---- phase D: per-bucket fixup (stable by (key30,idx)) + rank ----------
#pragma unroll
    for (int i = 0; i < IPT; i++) {
        int bk = tid * IPT + i;
        unsigned cb = sh.bcnt[bk];
        unsigned s0 = sh.bstart[bk];
        if (cb == 1) {
            sh.rank[sh.order[s0]] = (unsigned short)s0;
        } else if (cb > 1) {                       // Poisson(1): tiny buckets
            for (unsigned a = 1; a < cb; a++) {
                unsigned short px = sh.order[s0 + a];
                unsigned long long kx =
                    ((unsigned long long)sh.key[px] << 12) | px;
                int j = (int)a - 1;
                while (j >= 0) {
                    unsigned short py = sh.order[s0 + j];
                    unsigned long long ky =
                        ((unsigned long long)sh.key[py] << 12) | py;
                    if (ky <= kx) break;
                    sh.order[s0 + j + 1] = py;
                    j--;
                }
                sh.order[s0 + j + 1] = px;
            }
            for (unsigned a = 0; a < cb; a++)
                sh.rank[sh.order[s0 + a]] = (unsigned short)(s0 + a);
        }
    }
    __syncthreads();

    // ---- steepest-descent pointer + claim init (key/bcnt now dead) ---------
#pragma unroll
    for (int i = 0; i < IPT; i++) {
        int p = tid * IPT + i;
        int r = p >> 6, cc = p & 63;
        int best = p, bestr = sh.rank[p];
        for (int k = 0; k < nOff; k++) {
            int rr = r + drs[k], c2 = cc + dcs[k];
            if (rr >= 0 && rr < HW && c2 >= 0 && c2 < HW) {
                int q  = rr * HW + c2;
                int rq = sh.rank[q];
                if (rq < bestr) { bestr = rq; best = q; }
            }
        }
        sh.F[p]    = (unsigned short)best;
        sh.key[p]  = FULL;                          // claimY
        sh.bcnt[p] = FULL;                          // claimE
    }
    __syncthreads();

    // ---- pointer jumping until converged (benign forward-jump races) -------
    int changed = 1;
    while (__syncthreads_or(changed)) {
        changed = 0;
#pragma unroll
        for (int i = 0; i < IPT; i++) {
            int p = tid * IPT + i;
            int f = sh.F[p];
            int g = sh.F[f];
            if (g != f) { sh.F[p] = (unsigned short)g; changed = 1; }
        }
    }

    // ---- single-pass edge emission (per-thread atomic slot alloc) ----------
#pragma unroll
    for (int i = 0; i < IPT; i++) {
        int p = tid * IPT + i;
        int t = sh.rank[p];
        int r = p >> 6, cc = p & 63;
        unsigned short fs[8]; int nf = 0;
        for (int k = 0; k < nOff; k++) {
            int rr = r + drs[k], c2 = cc + dcs[k];
            if (rr >= 0 && rr < HW && c2 >= 0 && c2 < HW) {
                int q = rr * HW + c2;
                if (sh.rank[q] < t) {
                    unsigned short f = sh.F[q];
                    bool dup = false;
                    for (int j = 0; j < nf; j++) if (fs[j] == f) dup = true;
                    if (!dup) fs[nf++] = f;
                }
            }
        }
        if (nf >= 2) {
            int base = atomicAdd(&sh.ne, nf - 1);
            unsigned long long vb =
                ((unsigned long long)__float_as_uint(sh.val[p]) << 24) |
                ((unsigned long long)fs[0] << 12);
            for (int j = 1; j < nf; j++) {
                int slot = base + j - 1;
                if (slot < EDGE_CAP) {
                    sh.edges[slot] = vb | fs[j];
                    sh.ekey[slot]  = (unsigned short)(t * 8 + j); // total order
                }
            }
        }
    }
    __syncthreads();

    // ---- block-wide parallel Kruskal (root-cached, 2 barriers/round) -------
    {
        unsigned short*       mpar   = sh.mpar;
        const unsigned short* rank   = sh.rank;
        unsigned*             claimY = sh.key;     // aliases dead key[]
        unsigned*             claimE = sh.bcnt;    // aliases dead bcnt[]
        const int ne = sh.ne < EDGE_CAP ? sh.ne : EDGE_CAP;

        double S2 = 0.0; float pmax = 0.f; int has = 0;

        unsigned actmask = 0;
        unsigned short ya[KMAX], ea[KMAX], kks[KMAX];
        float          va[KMAX];
        // one-time init: load records; cache endpoints (they are minima and
        // thus on the find path forever: find(cached) == find(endpoint))
#pragma unroll
        for (int k = 0; k < KMAX; k++) {
            int slot = tid + k * BT;
            if (slot < ne) {
                unsigned long long rec = sh.edges[slot];
                ya[k]  = (unsigned short)((rec >> 12) & 0xFFFu);
                ea[k]  = (unsigned short)(rec & 0xFFFu);
                va[k]  = __uint_as_float((unsigned)(rec >> 24));
                kks[k] = sh.ekey[slot];
                actmask |= 1u << k;
            }
        }

        unsigned prefix = 0xFFFF0000u;   // decreases each round -> stale claims
                                         // always look "larger than any current"
        int any = __syncthreads_or(actmask != 0);
        while (any) {
            unsigned claimed = 0;
            // phase 1: short finds from cached roots, post prefixed claims
#pragma unroll
            for (int k = 0; k < KMAX; k++) if (actmask & (1u << k)) {
                int fa = phfind(mpar, ya[k]);      // 0-2 hops after round 1
                int fb = phfind(mpar, ea[k]);
                if (fa == fb) { actmask &= ~(1u << k); continue; }
                int eld, yng;
                if (rank[fa] < rank[fb]) { eld = fa; yng = fb; }
                else                     { eld = fb; yng = fa; }
                ya[k] = (unsigned short)yng;       // refresh cache
                ea[k] = (unsigned short)eld;
                unsigned kk = prefix | kks[k];
                atomicMin(&claimY[yng], kk);       // I want to merge yng away
                atomicMin(&claimE[eld], kk);       // I currently see eld as elder
                claimed |= 1u << k;
            }
            __syncthreads();
            // phase 2: commit iff (1) min young-claim of y is me (this round)
            //                     (2) no current-round edge has y as elder
            //          elder sharing is free -> whole stars commit per round
#pragma unroll
            for (int k = 0; k < KMAX; k++) if (claimed & (1u << k)) {
                unsigned kk = prefix | kks[k];
                if (claimY[ya[k]] == kk && claimE[ya[k]] > kk) {
                    int yng = ya[k];
                    float p = va[k] - sh.val[yng]; // birth = young root's value
                    if (p > 0.f) {
                        S2 += (double)p * (double)p;
                        if (p > pmax) pmax = p;
                        has = 1;
                    }
                    mpar[yng] = ea[k];
                    actmask &= ~(1u << k);
                }
            }
            prefix -= 0x10000u;              // no claim reset needed
            // end-of-round barrier doubles as the loop-condition reduction
            any = __syncthreads_or(actmask != 0);
        }

        // block reduction
#pragma unroll
        for (int off = 16; off; off >>= 1) {
            S2 += __shfl_down_sync(FULL, S2, off);
            float pm = __shfl_down_sync(FULL, pmax, off);
            pmax = fmaxf(pmax, pm);
            has |= __shfl_down_sync(FULL, has, off);
        }
        if (lane == 0) { sh.rS2[warp] = S2; sh.rPM[warp] = pmax; sh.rHas[warp] = has; }
        __syncthreads();

        if (tid == 0) {
            double tS2 = 0.0; float tPM = 0.f; int tH = 0;
            for (int w = 0; w < 32; w++) {
                tS2 += sh.rS2[w];
                tPM  = fmaxf(tPM, sh.rPM[w]);
                tH  |= sh.rHas[w];
            }
            TaskRes r;
            r.s2 = tS2; r.pmax = tPM; r.has = tH;
            r.vfirst = sh.val[sh.order[0]];       // essential birth (global min)
            g_res[task] = r;
            __threadfence();
            unsigned old = atomicAdd(&g_ctr, 1u);
            if (old == NTASK - 1) {               // last block: compute the loss
                __threadfence();
                volatile TaskRes* gr = g_res;
                const int nfx[3] = {0, 0, 1};
                const int nf1[3] = {0, 1, 0};
                double loss = 0.0;
                for (int im = 0; im < 12; im++) {
                    int ci = im % 3;
                    double s2a = gr[im*2].s2;   float pma = gr[im*2].pmax;
                    int    ha  = gr[im*2].has;  float vf  = gr[im*2].vfirst;
                    double s2b = gr[im*2+1].s2; float pmb = gr[im*2+1].pmax;
                    int    hb  = gr[im*2+1].has;
                    double h0 = (double)vf * (double)vf + s2a;
                    if (nfx[ci]) {
                        if (ha) { double p = pma; h0 += (1.0-p)*(1.0-p) - p*p; }
                        else     h0 += 1.0;
                    }
                    double h1 = s2b;
                    if (nf1[ci]) {
                        if (hb) { double p = pmb; h1 += (1.0-p)*(1.0-p) - p*p; }
                        else     h1 += 1.0;
                    }
                    loss += h0 + h1;
                }
                out[0] = (float)(loss * 0.25);
                atomicSub(&g_ctr, (unsigned)NTASK);   // reset for next launch
            }
        }
    }
}

extern "C" void kernel_launch(void* const* d_in, const int* in_sizes, int n_in,
                              void* d_out, int out_size)
{
    (void)in_sizes; (void)n_in; (void)out_size;
    const float* x = (const float*)d_in[0];
    cudaFuncSetAttribute(uf_kernel, cudaFuncAttributeMaxDynamicSharedMemorySize,
                         (int)sizeof(Shm));
    uf_kernel<<<NTASK, BT, sizeof(Shm)>>>(x, (float*)d_out);
}